// round 1
// baseline (speedup 1.0000x reference)
#include <cuda_runtime.h>
#include <cstdint>

// Problem shapes (fixed by the dataset)
#define Nn 4
#define Cc 32
#define Dd 64
#define Hh 64
#define Ww 64
#define Dout 32
#define Hout 32
#define Wout 32

#define NPOINTS (Nn * Dout * Hout * Wout)            // 131072
#define GI_ELEMS ((long long)Nn * Cc * Dd * Hh * Ww) // 33554432
#define SPATIAL_OUT (Dout * Hout * Wout)             // 32768
#define SPATIAL_IN (Dd * Hh * Ww)                    // 262144

// -------------------- zero-fill grad_input region --------------------
__global__ void gs3d_zero_kernel(float4* __restrict__ p, int n4) {
    int i = blockIdx.x * blockDim.x + threadIdx.x;
    if (i < n4) p[i] = make_float4(0.f, 0.f, 0.f, 0.f);
}

// -------------------- main backward kernel --------------------
// One warp per grid point; lane == channel (C == 32).
__global__ void __launch_bounds__(256) gs3d_bwd_kernel(
    const float* __restrict__ gOut,   // [N, C, Do, Ho, Wo]
    const float* __restrict__ inp,    // [N, C, D, H, W]
    const float* __restrict__ grid,   // [N, Do, Ho, Wo, 3]
    float* __restrict__ gInp,         // [N, C, D, H, W]
    float* __restrict__ gGrid)        // [N, Do, Ho, Wo, 3]
{
    const int warp = (blockIdx.x * blockDim.x + threadIdx.x) >> 5;
    const int lane = threadIdx.x & 31;
    if (warp >= NPOINTS) return;

    const int p  = warp;          // flat point index over N*Do*Ho*Wo
    const int n  = p >> 15;       // / 32768
    const int sp = p & 32767;     // spatial index within Do*Ho*Wo

    // All lanes read the same 3 grid floats (warp broadcast).
    const float gx = grid[p * 3 + 0];
    const float gy = grid[p * 3 + 1];
    const float gz = grid[p * 3 + 2];

    // align_corners = true unnormalize
    const float ix = (gx + 1.f) * 0.5f * (float)(Ww - 1);
    const float iy = (gy + 1.f) * 0.5f * (float)(Hh - 1);
    const float iz = (gz + 1.f) * 0.5f * (float)(Dd - 1);

    const float ix0f = floorf(ix);
    const float iy0f = floorf(iy);
    const float iz0f = floorf(iz);
    const int ix0 = (int)ix0f;
    const int iy0 = (int)iy0f;
    const int iz0 = (int)iz0f;
    const float tx = ix - ix0f;
    const float ty = iy - iy0f;
    const float tz = iz - iz0f;

    // Per-lane channel pointers
    const long long cbase = ((long long)n * Cc + lane) * SPATIAL_IN;
    const float* ib = inp + cbase;
    float* gb = gInp + cbase;

    const float go = gOut[((long long)n * Cc + lane) * SPATIAL_OUT + sp];

    float gix = 0.f, giy = 0.f, giz = 0.f;

#pragma unroll
    for (int dz = 0; dz < 2; dz++) {
#pragma unroll
        for (int dy = 0; dy < 2; dy++) {
#pragma unroll
            for (int dx = 0; dx < 2; dx++) {
                const int xc = ix0 + dx;
                const int yc = iy0 + dy;
                const int zc = iz0 + dz;
                const bool inb = ((unsigned)xc < (unsigned)Ww) &
                                 ((unsigned)yc < (unsigned)Hh) &
                                 ((unsigned)zc < (unsigned)Dd);
                if (inb) {
                    const int off = (zc << 12) + (yc << 6) + xc;
                    const float wx = dx ? tx : 1.f - tx;
                    const float wy = dy ? ty : 1.f - ty;
                    const float wz = dz ? tz : 1.f - tz;
                    const float v = __ldg(ib + off);
                    atomicAdd(gb + off, wx * wy * wz * go);  // RED (no return)
                    const float gv = go * v;
                    gix += gv * (dx ? 1.f : -1.f) * wy * wz;
                    giy += gv * wx * (dy ? 1.f : -1.f) * wz;
                    giz += gv * wx * wy * (dz ? 1.f : -1.f);
                }
            }
        }
    }

    // Warp reduction across channels (lanes)
#pragma unroll
    for (int o = 16; o > 0; o >>= 1) {
        gix += __shfl_xor_sync(0xFFFFFFFFu, gix, o);
        giy += __shfl_xor_sync(0xFFFFFFFFu, giy, o);
        giz += __shfl_xor_sync(0xFFFFFFFFu, giz, o);
    }

    if (lane == 0) {
        gGrid[p * 3 + 0] = gix * 0.5f * (float)(Ww - 1);
        gGrid[p * 3 + 1] = giy * 0.5f * (float)(Hh - 1);
        gGrid[p * 3 + 2] = giz * 0.5f * (float)(Dd - 1);
    }
}

extern "C" void kernel_launch(void* const* d_in, const int* in_sizes, int n_in,
                              void* d_out, int out_size) {
    const float* gOut = (const float*)d_in[0];  // grad_output
    const float* inp  = (const float*)d_in[1];  // input
    const float* grid = (const float*)d_in[2];  // grid
    float* out = (float*)d_out;

    float* gInp  = out;                 // [N,C,D,H,W]
    float* gGrid = out + GI_ELEMS;      // [N,Do,Ho,Wo,3]

    // Zero grad_input region (d_out is poisoned before timing)
    {
        const int n4 = (int)(GI_ELEMS / 4);  // 8,388,608 float4
        const int threads = 256;
        const int blocks = (n4 + threads - 1) / threads;
        gs3d_zero_kernel<<<blocks, threads>>>((float4*)gInp, n4);
    }

    // Main backward: one warp per grid point
    {
        const int threads = 256;                              // 8 warps / block
        const int blocks = (NPOINTS * 32) / threads;          // 16384
        gs3d_bwd_kernel<<<blocks, threads>>>(gOut, inp, grid, gInp, gGrid);
    }
}

// round 2
// speedup vs baseline: 1.8801x; 1.8801x over previous
#include <cuda_runtime.h>
#include <cstdint>
#include <cstddef>

// Fixed problem shapes
#define Nn 4
#define Cc 32
#define Dd 64
#define Hh 64
#define Ww 64
#define SPATIAL_IN (Dd * Hh * Ww)        // 262144
#define SPATIAL_OUT (32 * 32 * 32)       // 32768
#define NPOINTS (Nn * SPATIAL_OUT)       // 131072
#define GI_ELEMS ((size_t)Nn * Cc * SPATIAL_IN)  // 33554432

// Channels-last scratch (module-static device memory: allowed)
__device__ float g_inp_t[(size_t)Nn * SPATIAL_IN * Cc];    // input,  [N][S_in][C]
__device__ float g_gout_t[(size_t)Nn * SPATIAL_OUT * Cc];  // gOut,   [N][S_out][C]
__device__ float g_ginp_t[(size_t)Nn * SPATIAL_IN * Cc];   // gInp acc, [N][S_in][C]

// ---------------- zero-fill (float4) ----------------
__global__ void gs3d_zero_kernel(float4* __restrict__ p, int n4) {
    int i = blockIdx.x * blockDim.x + threadIdx.x;
    if (i < n4) p[i] = make_float4(0.f, 0.f, 0.f, 0.f);
}

// ---------------- [N][C][S] -> [N][S][C] ----------------
template <int S>
__global__ void transpose_cs(const float* __restrict__ src, float* __restrict__ dst) {
    __shared__ float tile[32][33];
    const int n = blockIdx.y;
    const int s0 = blockIdx.x * 32;
    const int tx = threadIdx.x, ty = threadIdx.y;
#pragma unroll
    for (int i = 0; i < 4; i++) {
        const int c = ty + i * 8;
        tile[c][tx] = src[((size_t)n * Cc + c) * S + s0 + tx];  // coalesced along s
    }
    __syncthreads();
#pragma unroll
    for (int i = 0; i < 4; i++) {
        const int s = ty + i * 8;
        dst[((size_t)n * S + s0 + s) * Cc + tx] = tile[tx][s];  // coalesced along c
    }
}

// ---------------- [N][S][C] -> [N][C][S]  (grad_input back) ----------------
__global__ void transpose_sc(const float* __restrict__ src, float* __restrict__ dst) {
    __shared__ float tile[32][33];
    const int n = blockIdx.y;
    const int s0 = blockIdx.x * 32;
    const int tx = threadIdx.x, ty = threadIdx.y;
#pragma unroll
    for (int i = 0; i < 4; i++) {
        const int s = ty + i * 8;
        tile[s][tx] = src[((size_t)n * SPATIAL_IN + s0 + s) * Cc + tx];  // coalesced along c
    }
    __syncthreads();
#pragma unroll
    for (int i = 0; i < 4; i++) {
        const int c = ty + i * 8;
        dst[((size_t)n * Cc + c) * SPATIAL_IN + s0 + tx] = tile[tx][c];  // coalesced along s
    }
}

// ---------------- main backward ----------------
// One 8-lane group per grid point (4 points per warp); each lane owns 4 channels (float4).
__global__ void __launch_bounds__(256) gs3d_main(
    const float* __restrict__ grid,  // [N, Do, Ho, Wo, 3]
    float* __restrict__ gGrid)       // [N, Do, Ho, Wo, 3]
{
    const int warp = (blockIdx.x * blockDim.x + threadIdx.x) >> 5;
    const int lane = threadIdx.x & 31;
    if (warp >= NPOINTS / 4) return;

    const int g   = lane >> 3;   // point within warp
    const int sub = lane & 7;    // channel-quad within point

    // 12 consecutive grid floats per warp, coalesced, then shuffled out.
    float gval = 0.f;
    if (lane < 12) gval = grid[(size_t)warp * 12 + lane];

    const int p  = warp * 4 + g;
    const int n  = p >> 15;
    const int sp = p & 32767;

    const float gx = __shfl_sync(0xFFFFFFFFu, gval, g * 3 + 0);
    const float gy = __shfl_sync(0xFFFFFFFFu, gval, g * 3 + 1);
    const float gz = __shfl_sync(0xFFFFFFFFu, gval, g * 3 + 2);

    // align_corners=1 unnormalize: 0.5*(dim-1) = 31.5
    const float ix = (gx + 1.f) * 31.5f;
    const float iy = (gy + 1.f) * 31.5f;
    const float iz = (gz + 1.f) * 31.5f;

    const float ix0f = floorf(ix);
    const float iy0f = floorf(iy);
    const float iz0f = floorf(iz);
    const int ix0 = (int)ix0f, iy0 = (int)iy0f, iz0 = (int)iz0f;
    const float tx = ix - ix0f, ty = iy - iy0f, tz = iz - iz0f;

    // grad_output, channels-last: 128B per group, coalesced float4
    const float4 go = __ldg((const float4*)(g_gout_t + ((size_t)n * SPATIAL_OUT + sp) * Cc) + sub);

    const size_t nbase = (size_t)n * SPATIAL_IN * Cc;
    float gix = 0.f, giy = 0.f, giz = 0.f;

#pragma unroll
    for (int dz = 0; dz < 2; dz++) {
#pragma unroll
        for (int dy = 0; dy < 2; dy++) {
#pragma unroll
            for (int dx = 0; dx < 2; dx++) {
                const int xc = ix0 + dx;
                const int yc = iy0 + dy;
                const int zc = iz0 + dz;
                const bool inb = ((unsigned)xc < (unsigned)Ww) &
                                 ((unsigned)yc < (unsigned)Hh) &
                                 ((unsigned)zc < (unsigned)Dd);
                if (inb) {
                    const int off = (zc << 12) + (yc << 6) + xc;
                    const size_t a = nbase + (size_t)off * Cc + sub * 4;
                    const float wx = dx ? tx : 1.f - tx;
                    const float wy = dy ? ty : 1.f - ty;
                    const float wz = dz ? tz : 1.f - tz;
                    const float w = wx * wy * wz;

                    const float4 v = __ldg((const float4*)(g_inp_t + a));

                    // Coalesced vectorized reduction: 16B per lane, 128B per group.
                    asm volatile(
                        "red.global.add.v4.f32 [%0], {%1, %2, %3, %4};"
                        :: "l"(g_ginp_t + a),
                           "f"(w * go.x), "f"(w * go.y), "f"(w * go.z), "f"(w * go.w)
                        : "memory");

                    const float gv = go.x * v.x + go.y * v.y + go.z * v.z + go.w * v.w;
                    gix += gv * (dx ? 1.f : -1.f) * wy * wz;
                    giy += gv * wx * (dy ? 1.f : -1.f) * wz;
                    giz += gv * wx * wy * (dz ? 1.f : -1.f);
                }
            }
        }
    }

    // Reduce across the 8 lanes of this point-group.
#pragma unroll
    for (int o = 4; o > 0; o >>= 1) {
        gix += __shfl_xor_sync(0xFFFFFFFFu, gix, o);
        giy += __shfl_xor_sync(0xFFFFFFFFu, giy, o);
        giz += __shfl_xor_sync(0xFFFFFFFFu, giz, o);
    }

    if (sub == 0) {
        gGrid[(size_t)p * 3 + 0] = gix * 31.5f;
        gGrid[(size_t)p * 3 + 1] = giy * 31.5f;
        gGrid[(size_t)p * 3 + 2] = giz * 31.5f;
    }
}

extern "C" void kernel_launch(void* const* d_in, const int* in_sizes, int n_in,
                              void* d_out, int out_size) {
    const float* gOut = (const float*)d_in[0];  // [N,C,Do,Ho,Wo]
    const float* inp  = (const float*)d_in[1];  // [N,C,D,H,W]
    const float* grid = (const float*)d_in[2];  // [N,Do,Ho,Wo,3]
    float* out = (float*)d_out;

    float* gInp  = out;              // [N,C,D,H,W]
    float* gGrid = out + GI_ELEMS;   // [N,Do,Ho,Wo,3]

    float *inp_t, *gout_t, *ginp_t;
    cudaGetSymbolAddress((void**)&inp_t,  g_inp_t);
    cudaGetSymbolAddress((void**)&gout_t, g_gout_t);
    cudaGetSymbolAddress((void**)&ginp_t, g_ginp_t);

    // 1) transpose grad_output to channels-last
    {
        dim3 blk(32, 8), grd(SPATIAL_OUT / 32, Nn);
        transpose_cs<SPATIAL_OUT><<<grd, blk>>>(gOut, gout_t);
    }
    // 2) transpose input to channels-last
    {
        dim3 blk(32, 8), grd(SPATIAL_IN / 32, Nn);
        transpose_cs<SPATIAL_IN><<<grd, blk>>>(inp, inp_t);
    }
    // 3) zero channels-last grad_input scratch
    {
        const int n4 = (int)(GI_ELEMS / 4);
        gs3d_zero_kernel<<<(n4 + 255) / 256, 256>>>((float4*)ginp_t, n4);
    }
    // 4) main backward (8 lanes per point, 4 points per warp)
    {
        const int warps = NPOINTS / 4;            // 32768
        const int threads = 256;                  // 8 warps/block
        gs3d_main<<<warps * 32 / threads, threads>>>(grid, gGrid);
    }
    // 5) transpose grad_input back to [N,C,D,H,W] into d_out
    {
        dim3 blk(32, 8), grd(SPATIAL_IN / 32, Nn);
        transpose_sc<<<grd, blk>>>(ginp_t, gInp);
    }
}

// round 3
// speedup vs baseline: 2.0328x; 1.0812x over previous
#include <cuda_runtime.h>
#include <cuda_fp16.h>
#include <cstdint>
#include <cstddef>

// Fixed problem shapes
#define Nn 4
#define Cc 32
#define Dd 64
#define Hh 64
#define Ww 64
#define SPATIAL_IN (Dd * Hh * Ww)        // 262144
#define SPATIAL_OUT (32 * 32 * 32)       // 32768
#define NPOINTS (Nn * SPATIAL_OUT)       // 131072
#define GI_ELEMS ((size_t)Nn * Cc * SPATIAL_IN)  // 33554432

#define OUT_TILES (SPATIAL_OUT / 32)     // 1024
#define IN_TILES  (SPATIAL_IN / 32)      // 8192

// Channels-last scratch (static device memory: allowed)
__device__ __half g_inp_t[(size_t)Nn * SPATIAL_IN * Cc];   // input  [N][S_in][C], fp16
__device__ float  g_gout_t[(size_t)Nn * SPATIAL_OUT * Cc]; // gOut   [N][S_out][C], fp32
__device__ float  g_ginp_t[(size_t)Nn * SPATIAL_IN * Cc];  // gInp accum, fp32

// ---------------- zero-fill (float4) ----------------
__global__ void gs3d_zero_kernel(float4* __restrict__ p, int n4) {
    int i = blockIdx.x * blockDim.x + threadIdx.x;
    if (i < n4) p[i] = make_float4(0.f, 0.f, 0.f, 0.f);
}

// ---------------- merged prep: transpose gOut (f32) + input (->fp16) ----------------
// blockDim (32, 8). blockIdx.x < OUT_TILES -> gOut tile; else input tile.
__global__ void gs3d_prep(const float* __restrict__ gOut, const float* __restrict__ inp) {
    __shared__ float tile[32][33];
    const int n  = blockIdx.y;
    const int tx = threadIdx.x, ty = threadIdx.y;

    if (blockIdx.x < OUT_TILES) {
        const int s0 = blockIdx.x * 32;
#pragma unroll
        for (int i = 0; i < 4; i++) {
            const int c = ty + i * 8;
            tile[c][tx] = gOut[((size_t)n * Cc + c) * SPATIAL_OUT + s0 + tx];
        }
        __syncthreads();
#pragma unroll
        for (int i = 0; i < 4; i++) {
            const int s = ty + i * 8;
            g_gout_t[((size_t)n * SPATIAL_OUT + s0 + s) * Cc + tx] = tile[tx][s];
        }
    } else {
        const int s0 = (blockIdx.x - OUT_TILES) * 32;
#pragma unroll
        for (int i = 0; i < 4; i++) {
            const int c = ty + i * 8;
            tile[c][tx] = inp[((size_t)n * Cc + c) * SPATIAL_IN + s0 + tx];
        }
        __syncthreads();
        // half2 store: lane tx -> r = tx>>4 selects s offset, cp = tx&15 channel-pair
        const int r  = tx >> 4;
        const int cp = tx & 15;
        __half2* dst = (__half2*)g_inp_t;
#pragma unroll
        for (int i = 0; i < 2; i++) {
            const int s = ty * 4 + i * 2 + r;
            const __half2 h = __floats2half2_rn(tile[2 * cp][s], tile[2 * cp + 1][s]);
            dst[((size_t)n * SPATIAL_IN + s0 + s) * (Cc / 2) + cp] = h;
        }
    }
}

// ---------------- [N][S][C] -> [N][C][S]  (grad_input back) ----------------
__global__ void transpose_sc(const float* __restrict__ src, float* __restrict__ dst) {
    __shared__ float tile[32][33];
    const int n = blockIdx.y;
    const int s0 = blockIdx.x * 32;
    const int tx = threadIdx.x, ty = threadIdx.y;
#pragma unroll
    for (int i = 0; i < 4; i++) {
        const int s = ty + i * 8;
        tile[s][tx] = src[((size_t)n * SPATIAL_IN + s0 + s) * Cc + tx];
    }
    __syncthreads();
#pragma unroll
    for (int i = 0; i < 4; i++) {
        const int c = ty + i * 8;
        dst[((size_t)n * Cc + c) * SPATIAL_IN + s0 + tx] = tile[tx][c];
    }
}

// ---------------- main backward ----------------
// One 8-lane group per grid point (4 points per warp); each lane owns 4 channels.
__global__ void __launch_bounds__(256) gs3d_main(
    const float* __restrict__ grid,  // [N, Do, Ho, Wo, 3]
    float* __restrict__ gGrid)       // [N, Do, Ho, Wo, 3]
{
    const int warp = (blockIdx.x * blockDim.x + threadIdx.x) >> 5;
    const int lane = threadIdx.x & 31;
    if (warp >= NPOINTS / 4) return;

    const int g   = lane >> 3;   // point within warp
    const int sub = lane & 7;    // channel-quad within point

    // 12 consecutive grid floats per warp, coalesced, then shuffled out.
    float gval = 0.f;
    if (lane < 12) gval = grid[(size_t)warp * 12 + lane];

    const int p  = warp * 4 + g;
    const int n  = p >> 15;
    const int sp = p & 32767;

    const float gx = __shfl_sync(0xFFFFFFFFu, gval, g * 3 + 0);
    const float gy = __shfl_sync(0xFFFFFFFFu, gval, g * 3 + 1);
    const float gz = __shfl_sync(0xFFFFFFFFu, gval, g * 3 + 2);

    // align_corners=1 unnormalize: 0.5*(dim-1) = 31.5
    const float ix = (gx + 1.f) * 31.5f;
    const float iy = (gy + 1.f) * 31.5f;
    const float iz = (gz + 1.f) * 31.5f;

    const float ix0f = floorf(ix);
    const float iy0f = floorf(iy);
    const float iz0f = floorf(iz);
    const int ix0 = (int)ix0f, iy0 = (int)iy0f, iz0 = (int)iz0f;
    const float tx = ix - ix0f, ty = iy - iy0f, tz = iz - iz0f;

    // grad_output, channels-last: 128B per group, coalesced float4
    const float4 go = __ldg((const float4*)(g_gout_t + ((size_t)n * SPATIAL_OUT + sp) * Cc) + sub);

    const size_t nbase_f = (size_t)n * SPATIAL_IN * Cc;        // float index base (scatter)
    const __half* ibase  = g_inp_t + (size_t)n * SPATIAL_IN * Cc;  // half base (gather)

    float gix = 0.f, giy = 0.f, giz = 0.f;

#pragma unroll
    for (int dz = 0; dz < 2; dz++) {
#pragma unroll
        for (int dy = 0; dy < 2; dy++) {
#pragma unroll
            for (int dx = 0; dx < 2; dx++) {
                const int xc = ix0 + dx;
                const int yc = iy0 + dy;
                const int zc = iz0 + dz;
                const bool inb = ((unsigned)xc < (unsigned)Ww) &
                                 ((unsigned)yc < (unsigned)Hh) &
                                 ((unsigned)zc < (unsigned)Dd);
                if (inb) {
                    const int off = (zc << 12) + (yc << 6) + xc;
                    const float wx = dx ? tx : 1.f - tx;
                    const float wy = dy ? ty : 1.f - ty;
                    const float wz = dz ? tz : 1.f - tz;
                    const float w = wx * wy * wz;

                    // fp16 gather: 4 channels = 8B per lane, 64B per group
                    const uint2 raw = __ldg((const uint2*)(ibase + (size_t)off * Cc + sub * 4));
                    const __half2 h01 = *reinterpret_cast<const __half2*>(&raw.x);
                    const __half2 h23 = *reinterpret_cast<const __half2*>(&raw.y);
                    const float2 v01 = __half22float2(h01);
                    const float2 v23 = __half22float2(h23);

                    // Coalesced vectorized reduction: 16B per lane, 128B per group.
                    asm volatile(
                        "red.global.add.v4.f32 [%0], {%1, %2, %3, %4};"
                        :: "l"(g_ginp_t + nbase_f + (size_t)off * Cc + sub * 4),
                           "f"(w * go.x), "f"(w * go.y), "f"(w * go.z), "f"(w * go.w)
                        : "memory");

                    const float gv = go.x * v01.x + go.y * v01.y + go.z * v23.x + go.w * v23.y;
                    gix += gv * (dx ? 1.f : -1.f) * wy * wz;
                    giy += gv * wx * (dy ? 1.f : -1.f) * wz;
                    giz += gv * wx * wy * (dz ? 1.f : -1.f);
                }
            }
        }
    }

    // Reduce across the 8 lanes of this point-group.
#pragma unroll
    for (int o = 4; o > 0; o >>= 1) {
        gix += __shfl_xor_sync(0xFFFFFFFFu, gix, o);
        giy += __shfl_xor_sync(0xFFFFFFFFu, giy, o);
        giz += __shfl_xor_sync(0xFFFFFFFFu, giz, o);
    }

    if (sub == 0) {
        gGrid[(size_t)p * 3 + 0] = gix * 31.5f;
        gGrid[(size_t)p * 3 + 1] = giy * 31.5f;
        gGrid[(size_t)p * 3 + 2] = giz * 31.5f;
    }
}

extern "C" void kernel_launch(void* const* d_in, const int* in_sizes, int n_in,
                              void* d_out, int out_size) {
    const float* gOut = (const float*)d_in[0];  // [N,C,Do,Ho,Wo]
    const float* inp  = (const float*)d_in[1];  // [N,C,D,H,W]
    const float* grid = (const float*)d_in[2];  // [N,Do,Ho,Wo,3]
    float* out = (float*)d_out;

    float* gInp  = out;              // [N,C,D,H,W]
    float* gGrid = out + GI_ELEMS;   // [N,Do,Ho,Wo,3]

    float* ginp_t;
    cudaGetSymbolAddress((void**)&ginp_t, g_ginp_t);

    // 1) merged prep: transpose gOut (f32) + input (fp16) to channels-last
    {
        dim3 blk(32, 8), grd(OUT_TILES + IN_TILES, Nn);
        gs3d_prep<<<grd, blk>>>(gOut, inp);
    }
    // 2) zero channels-last grad_input scratch (last before main: primes L2)
    {
        const int n4 = (int)(GI_ELEMS / 4);
        gs3d_zero_kernel<<<(n4 + 255) / 256, 256>>>((float4*)ginp_t, n4);
    }
    // 3) main backward
    {
        const int warps = NPOINTS / 4;            // 32768
        const int threads = 256;
        gs3d_main<<<warps * 32 / threads, threads>>>(grid, gGrid);
    }
    // 4) transpose grad_input back to [N,C,D,H,W] into d_out
    {
        dim3 blk(32, 8), grd(IN_TILES, Nn);
        transpose_sc<<<grd, blk>>>(ginp_t, gInp);
    }
}